// round 1
// baseline (speedup 1.0000x reference)
#include <cuda_runtime.h>
#include <math.h>

#define NB    8
#define DIM   256
#define YD    4096
#define HH    8
#define DD    64
#define INNER 512
#define WW    256          // kv tokens
#define ASCALE 0.125f      // D^-0.5

// ---------------- scratch (device globals; no allocation) ----------------
__device__ float g_Q0[NB * INNER * YD];          // [b, o, y]
__device__ float g_Q1[NB * INNER * YD];
__device__ float g_KV0[NB * 2 * INNER * WW];     // [b, o, w]
__device__ float g_KV1[NB * 2 * INNER * WW];
__device__ float g_O0[(size_t)NB * YD * INNER];  // [b, y, h*64+d]
__device__ float g_O1[(size_t)NB * YD * INNER];

// =====================================================================
// Kernel 1: Q projection.  C[b,m,n] = sum_k A[m,k] * X[b,k,n]
// M=512, K=256, N=4096.  128x128 tile, BK=8, 8x8 microtile, 256 thr.
// =====================================================================
__global__ __launch_bounds__(256) void qproj_kernel(
    const float* __restrict__ A, const float* __restrict__ X,
    float* __restrict__ C)
{
    const int M = INNER, K = DIM, N = YD;
    const int b  = blockIdx.z;
    const int n0 = blockIdx.x * 128;
    const int m0 = blockIdx.y * 128;
    const float* Bp = X + (size_t)b * K * N;
    float*       Cp = C + (size_t)b * M * N;

    __shared__ float As[8][128];
    __shared__ float Bs[8][128];

    const int t  = threadIdx.x;
    const int tx = t & 15, ty = t >> 4;

    float acc[8][8];
#pragma unroll
    for (int i = 0; i < 8; i++)
#pragma unroll
        for (int j = 0; j < 8; j++) acc[i][j] = 0.f;

    for (int k0 = 0; k0 < K; k0 += 8) {
        {   // A tile: 128 x 8, transpose into As[k][m]
            int m = t >> 1, k4 = (t & 1) * 4;
            float4 a = *(const float4*)&A[(m0 + m) * K + k0 + k4];
            As[k4 + 0][m] = a.x; As[k4 + 1][m] = a.y;
            As[k4 + 2][m] = a.z; As[k4 + 3][m] = a.w;
        }
        {   // B tile: 8 x 128, direct
            int kk = t >> 5, n4 = (t & 31) * 4;
            *(float4*)&Bs[kk][n4] = *(const float4*)&Bp[(size_t)(k0 + kk) * N + n0 + n4];
        }
        __syncthreads();
#pragma unroll
        for (int k = 0; k < 8; k++) {
            float a[8], bb[8];
            *(float4*)&a[0]  = *(const float4*)&As[k][ty * 8];
            *(float4*)&a[4]  = *(const float4*)&As[k][ty * 8 + 4];
            *(float4*)&bb[0] = *(const float4*)&Bs[k][tx * 8];
            *(float4*)&bb[4] = *(const float4*)&Bs[k][tx * 8 + 4];
#pragma unroll
            for (int i = 0; i < 8; i++)
#pragma unroll
                for (int j = 0; j < 8; j++) acc[i][j] += a[i] * bb[j];
        }
        __syncthreads();
    }
#pragma unroll
    for (int i = 0; i < 8; i++) {
        size_t row = (size_t)(m0 + ty * 8 + i) * N + n0 + tx * 8;
        *(float4*)&Cp[row]     = *(float4*)&acc[i][0];
        *(float4*)&Cp[row + 4] = *(float4*)&acc[i][4];
    }
}

// =====================================================================
// Kernel 2: KV projection.  C[b,o,w] = sum_{n,pq} Wkv[o, n*16+pq] * x[b,n,w*16+pq]
// M=1024, N=256 (w), K=4096.  BM=128, BN=64, BK=16 (one n per tile), 8x4 micro.
// =====================================================================
__global__ __launch_bounds__(256) void kvproj_kernel(
    const float* __restrict__ Wkv, const float* __restrict__ X,
    float* __restrict__ C)
{
    const int M = 2 * INNER, N = WW, K = DIM * 16;
    const int b  = blockIdx.z;
    const int n0 = blockIdx.x * 64;     // w offset
    const int m0 = blockIdx.y * 128;
    const float* xp = X + (size_t)b * DIM * YD;
    float*       Cp = C + (size_t)b * M * N;

    __shared__ float As[16][128];
    __shared__ float Bs[16][68];

    const int t  = threadIdx.x;
    const int tx = t & 15, ty = t >> 4;

    float acc[8][4];
#pragma unroll
    for (int i = 0; i < 8; i++)
#pragma unroll
        for (int j = 0; j < 4; j++) acc[i][j] = 0.f;

    for (int nt = 0; nt < DIM; nt++) {
        const int k0 = nt * 16;
        {   // A tile 128 x 16, transpose
            int m = t >> 1, k8 = (t & 1) * 8;
            float4 a0 = *(const float4*)&Wkv[(size_t)(m0 + m) * K + k0 + k8];
            float4 a1 = *(const float4*)&Wkv[(size_t)(m0 + m) * K + k0 + k8 + 4];
            As[k8 + 0][m] = a0.x; As[k8 + 1][m] = a0.y;
            As[k8 + 2][m] = a0.z; As[k8 + 3][m] = a0.w;
            As[k8 + 4][m] = a1.x; As[k8 + 5][m] = a1.y;
            As[k8 + 6][m] = a1.z; As[k8 + 7][m] = a1.w;
        }
        {   // B tile: contiguous 1024 floats = x[b, nt, n0*16 .. n0*16+1024)
            const float* src = xp + (size_t)nt * YD + n0 * 16;
            float4 v = *(const float4*)&src[t * 4];
            int w = t >> 2, pq0 = (t & 3) * 4;
            Bs[pq0 + 0][w] = v.x; Bs[pq0 + 1][w] = v.y;
            Bs[pq0 + 2][w] = v.z; Bs[pq0 + 3][w] = v.w;
        }
        __syncthreads();
#pragma unroll
        for (int k = 0; k < 16; k++) {
            float a[8], bb[4];
            *(float4*)&a[0]  = *(const float4*)&As[k][ty * 8];
            *(float4*)&a[4]  = *(const float4*)&As[k][ty * 8 + 4];
            *(float4*)&bb[0] = *(const float4*)&Bs[k][tx * 4];
#pragma unroll
            for (int i = 0; i < 8; i++)
#pragma unroll
                for (int j = 0; j < 4; j++) acc[i][j] += a[i] * bb[j];
        }
        __syncthreads();
    }
#pragma unroll
    for (int i = 0; i < 8; i++) {
        size_t row = (size_t)(m0 + ty * 8 + i) * N + n0 + tx * 4;
        *(float4*)&Cp[row] = *(float4*)&acc[i][0];
    }
}

// =====================================================================
// Kernel 3: attention.  Per (b, h): q[4096,64] x k/v[256,64].
// K,V staged fully in SMEM (padded stride 68). Warp-per-row.
// Output layout: O[b, y, h, d]  (d contiguous).
// grid: (16 q-chunks of 256 rows, H, B); 256 threads.
// =====================================================================
__global__ __launch_bounds__(256) void attn_kernel(
    const float* __restrict__ Q, const float* __restrict__ KV,
    float* __restrict__ O)
{
    const int b   = blockIdx.z;
    const int h   = blockIdx.y;
    const int i0c = blockIdx.x * 256;

    extern __shared__ float sm[];
    float* ks = sm;                    // 256 * 68
    float* vs = ks + 256 * 68;         // 256 * 68
    float* qs = vs + 256 * 68;         // 64 * 68
    float* ps = qs + 64 * 68;          // 8 * 256

    const int t    = threadIdx.x;
    const int lane = t & 31;
    const int w    = t >> 5;

    const float* Kbase = KV + ((size_t)b * 1024 + h * 64) * WW;
    const float* Vbase = KV + ((size_t)b * 1024 + 512 + h * 64) * WW;

    // stage K and V (transpose to [j][d])
    for (int idx = t; idx < 64 * 64; idx += 256) {
        int d  = idx >> 6;
        int j4 = (idx & 63) * 4;
        float4 k4 = *(const float4*)&Kbase[d * WW + j4];
        ks[(j4 + 0) * 68 + d] = k4.x; ks[(j4 + 1) * 68 + d] = k4.y;
        ks[(j4 + 2) * 68 + d] = k4.z; ks[(j4 + 3) * 68 + d] = k4.w;
        float4 v4 = *(const float4*)&Vbase[d * WW + j4];
        vs[(j4 + 0) * 68 + d] = v4.x; vs[(j4 + 1) * 68 + d] = v4.y;
        vs[(j4 + 2) * 68 + d] = v4.z; vs[(j4 + 3) * 68 + d] = v4.w;
    }
    __syncthreads();

    for (int qt = 0; qt < 4; qt++) {
        const int i0 = i0c + qt * 64;
        __syncthreads();   // protect qs reuse
        for (int idx = t; idx < 64 * 16; idx += 256) {
            int d   = idx >> 4;
            int ii4 = (idx & 15) * 4;
            float4 q4 = *(const float4*)&Q[((size_t)b * INNER + h * 64 + d) * YD + i0 + ii4];
            qs[(ii4 + 0) * 68 + d] = q4.x; qs[(ii4 + 1) * 68 + d] = q4.y;
            qs[(ii4 + 2) * 68 + d] = q4.z; qs[(ii4 + 3) * 68 + d] = q4.w;
        }
        __syncthreads();

        for (int p = 0; p < 8; p++) {
            const int i = p * 8 + w;           // row within tile
            // ---- dots: each lane owns j = lane + 32*jj ----
            float dot[8];
#pragma unroll
            for (int jj = 0; jj < 8; jj++) dot[jj] = 0.f;
#pragma unroll
            for (int d4 = 0; d4 < 64; d4 += 4) {
                float4 q4 = *(const float4*)&qs[i * 68 + d4];
#pragma unroll
                for (int jj = 0; jj < 8; jj++) {
                    int j = lane + jj * 32;
                    float4 k4 = *(const float4*)&ks[j * 68 + d4];
                    dot[jj] += q4.x * k4.x + q4.y * k4.y + q4.z * k4.z + q4.w * k4.w;
                }
            }
            // ---- softmax over 256 ----
            float mx = -1e30f;
#pragma unroll
            for (int jj = 0; jj < 8; jj++) { dot[jj] *= ASCALE; mx = fmaxf(mx, dot[jj]); }
#pragma unroll
            for (int off = 16; off; off >>= 1)
                mx = fmaxf(mx, __shfl_xor_sync(0xffffffffu, mx, off));
            float e[8], s = 0.f;
#pragma unroll
            for (int jj = 0; jj < 8; jj++) { e[jj] = __expf(dot[jj] - mx); s += e[jj]; }
#pragma unroll
            for (int off = 16; off; off >>= 1)
                s += __shfl_xor_sync(0xffffffffu, s, off);
            float inv = 1.f / s;
            __syncwarp();   // prev pass readers done before overwrite
#pragma unroll
            for (int jj = 0; jj < 8; jj++) ps[w * 256 + lane + jj * 32] = e[jj] * inv;
            __syncwarp();
            // ---- o = P @ V : lane owns d = 2*lane, 2*lane+1 ----
            float ox = 0.f, oy = 0.f;
#pragma unroll 4
            for (int j0 = 0; j0 < 256; j0 += 4) {
                float4 p4 = *(const float4*)&ps[w * 256 + j0];
                float2 v0 = *(const float2*)&vs[(j0 + 0) * 68 + lane * 2];
                float2 v1 = *(const float2*)&vs[(j0 + 1) * 68 + lane * 2];
                float2 v2 = *(const float2*)&vs[(j0 + 2) * 68 + lane * 2];
                float2 v3 = *(const float2*)&vs[(j0 + 3) * 68 + lane * 2];
                ox += p4.x * v0.x + p4.y * v1.x + p4.z * v2.x + p4.w * v3.x;
                oy += p4.x * v0.y + p4.y * v1.y + p4.z * v2.y + p4.w * v3.y;
            }
            float2 o2; o2.x = ox; o2.y = oy;
            *(float2*)&O[(((size_t)b * YD + i0 + i) * HH + h) * 64 + lane * 2] = o2;
        }
    }
}

// =====================================================================
// Kernel 4: out proj (NT) + residual fuse.
// out[b,c,y] = 0.5*( sum_o W0[c,o]*O0[b,y,o] + W1[c,o]*O1[b,y,o]
//                    + x0 + x1 ) + 0.5*(b0[c]+b1[c])
// M=256, N=4096, K=512 per phase. BM=BN=128, BK=16, 8x8 micro.
// =====================================================================
__global__ __launch_bounds__(256) void outproj_kernel(
    const float* __restrict__ W0, const float* __restrict__ O0,
    const float* __restrict__ W1, const float* __restrict__ O1,
    const float* __restrict__ b0, const float* __restrict__ b1,
    const float* __restrict__ x0, const float* __restrict__ x1,
    float* __restrict__ out)
{
    const int b  = blockIdx.z;
    const int n0 = blockIdx.x * 128;
    const int m0 = blockIdx.y * 128;

    __shared__ float Ws[16][128];
    __shared__ float Bs[16][128];

    const int t  = threadIdx.x;
    const int tx = t & 15, ty = t >> 4;

    float acc[8][8];
#pragma unroll
    for (int i = 0; i < 8; i++)
#pragma unroll
        for (int j = 0; j < 8; j++) acc[i][j] = 0.f;

    const float* Ops[2] = { O0 + (size_t)b * YD * INNER, O1 + (size_t)b * YD * INNER };
    const float* Wsrc[2] = { W0, W1 };

    for (int ph = 0; ph < 2; ph++) {
        const float* W  = Wsrc[ph];
        const float* Op = Ops[ph];
        for (int k0 = 0; k0 < INNER; k0 += 16) {
            {   int m = t >> 1, k8 = (t & 1) * 8;
                float4 a0 = *(const float4*)&W[(size_t)(m0 + m) * INNER + k0 + k8];
                float4 a1 = *(const float4*)&W[(size_t)(m0 + m) * INNER + k0 + k8 + 4];
                Ws[k8 + 0][m] = a0.x; Ws[k8 + 1][m] = a0.y;
                Ws[k8 + 2][m] = a0.z; Ws[k8 + 3][m] = a0.w;
                Ws[k8 + 4][m] = a1.x; Ws[k8 + 5][m] = a1.y;
                Ws[k8 + 6][m] = a1.z; Ws[k8 + 7][m] = a1.w;
            }
            {   int n = t >> 1, k8 = (t & 1) * 8;
                float4 a0 = *(const float4*)&Op[(size_t)(n0 + n) * INNER + k0 + k8];
                float4 a1 = *(const float4*)&Op[(size_t)(n0 + n) * INNER + k0 + k8 + 4];
                Bs[k8 + 0][n] = a0.x; Bs[k8 + 1][n] = a0.y;
                Bs[k8 + 2][n] = a0.z; Bs[k8 + 3][n] = a0.w;
                Bs[k8 + 4][n] = a1.x; Bs[k8 + 5][n] = a1.y;
                Bs[k8 + 6][n] = a1.z; Bs[k8 + 7][n] = a1.w;
            }
            __syncthreads();
#pragma unroll
            for (int k = 0; k < 16; k++) {
                float a[8], bb[8];
                *(float4*)&a[0]  = *(const float4*)&Ws[k][ty * 8];
                *(float4*)&a[4]  = *(const float4*)&Ws[k][ty * 8 + 4];
                *(float4*)&bb[0] = *(const float4*)&Bs[k][tx * 8];
                *(float4*)&bb[4] = *(const float4*)&Bs[k][tx * 8 + 4];
#pragma unroll
                for (int i = 0; i < 8; i++)
#pragma unroll
                    for (int j = 0; j < 8; j++) acc[i][j] += a[i] * bb[j];
            }
            __syncthreads();
        }
    }

#pragma unroll
    for (int i = 0; i < 8; i++) {
        const int c = m0 + ty * 8 + i;
        const float bias = 0.5f * (b0[c] + b1[c]);
#pragma unroll
        for (int j4 = 0; j4 < 8; j4 += 4) {
            size_t idx = ((size_t)b * DIM + c) * YD + n0 + tx * 8 + j4;
            float4 xa = *(const float4*)&x0[idx];
            float4 xb = *(const float4*)&x1[idx];
            float4 r;
            r.x = 0.5f * (acc[i][j4 + 0] + xa.x + xb.x) + bias;
            r.y = 0.5f * (acc[i][j4 + 1] + xa.y + xb.y) + bias;
            r.z = 0.5f * (acc[i][j4 + 2] + xa.z + xb.z) + bias;
            r.w = 0.5f * (acc[i][j4 + 3] + xa.w + xb.w) + bias;
            *(float4*)&out[idx] = r;
        }
    }
}

// =====================================================================
extern "C" void kernel_launch(void* const* d_in, const int* in_sizes, int n_in,
                              void* d_out, int out_size)
{
    const float* x0    = (const float*)d_in[0];
    const float* x1    = (const float*)d_in[1];
    const float* Wq0   = (const float*)d_in[2];
    const float* Wkv0  = (const float*)d_in[3];
    const float* Wq1   = (const float*)d_in[4];
    const float* Wkv1  = (const float*)d_in[5];
    const float* Wout0 = (const float*)d_in[6];
    const float* bout0 = (const float*)d_in[7];
    const float* Wout1 = (const float*)d_in[8];
    const float* bout1 = (const float*)d_in[9];
    float* out = (float*)d_out;

    float *Q0, *Q1, *KV0, *KV1, *O0, *O1;
    cudaGetSymbolAddress((void**)&Q0,  g_Q0);
    cudaGetSymbolAddress((void**)&Q1,  g_Q1);
    cudaGetSymbolAddress((void**)&KV0, g_KV0);
    cudaGetSymbolAddress((void**)&KV1, g_KV1);
    cudaGetSymbolAddress((void**)&O0,  g_O0);
    cudaGetSymbolAddress((void**)&O1,  g_O1);

    const int attn_smem = (2 * 256 * 68 + 64 * 68 + 8 * 256) * (int)sizeof(float);
    cudaFuncSetAttribute(attn_kernel, cudaFuncAttributeMaxDynamicSharedMemorySize, attn_smem);

    dim3 blk(256);
    // Q projections
    qproj_kernel<<<dim3(YD / 128, INNER / 128, NB), blk>>>(Wq0, x0, Q0);
    qproj_kernel<<<dim3(YD / 128, INNER / 128, NB), blk>>>(Wq1, x1, Q1);
    // KV projections
    kvproj_kernel<<<dim3(WW / 64, (2 * INNER) / 128, NB), blk>>>(Wkv0, x0, KV0);
    kvproj_kernel<<<dim3(WW / 64, (2 * INNER) / 128, NB), blk>>>(Wkv1, x1, KV1);
    // Cross attention: out0 = attend(q0, k1, v1); out1 = attend(q1, k0, v0)
    attn_kernel<<<dim3(YD / 256, HH, NB), blk, attn_smem>>>(Q0, KV1, O0);
    attn_kernel<<<dim3(YD / 256, HH, NB), blk, attn_smem>>>(Q1, KV0, O1);
    // Out projections + residual fuse
    outproj_kernel<<<dim3(YD / 128, DIM / 128, NB), blk>>>(
        Wout0, O0, Wout1, O1, bout0, bout1, x0, x1, out);
}

// round 2
// speedup vs baseline: 1.5234x; 1.5234x over previous
#include <cuda_runtime.h>
#include <math.h>

#define NB    8
#define DIM   256
#define YD    4096
#define HH    8
#define INNER 512
#define WW    256
#define ASCALE 0.125f

typedef unsigned long long u64;

__device__ __forceinline__ u64 ffma2(u64 a, u64 b, u64 c) {
    u64 d; asm("fma.rn.f32x2 %0, %1, %2, %3;" : "=l"(d) : "l"(a), "l"(b), "l"(c)); return d;
}
__device__ __forceinline__ u64 dup2(float x) {
    u64 d; asm("mov.b64 %0, {%1, %2};" : "=l"(d) : "f"(x), "f"(x)); return d;
}
__device__ __forceinline__ float2 u2f(u64 v) {
    float2 r; asm("mov.b64 {%0, %1}, %2;" : "=f"(r.x), "=f"(r.y) : "l"(v)); return r;
}

// ---------------- scratch ----------------
__device__ float g_Q0[NB * INNER * YD];
__device__ float g_Q1[NB * INNER * YD];
__device__ float g_KV0[NB * 2 * INNER * WW];
__device__ float g_KV1[NB * 2 * INNER * WW];
__device__ float g_O0[(size_t)NB * YD * INNER];
__device__ float g_O1[(size_t)NB * YD * INNER];

// =====================================================================
// Q projection (both streams). C[b,m,n] = sum_k A[m,k] X[b,k,n]
// M=512,K=256,N=4096. 128x128 tile, BK=8, micro 8m x 8n (m packed pairs).
// =====================================================================
__global__ __launch_bounds__(256) void qproj_kernel(
    const float* __restrict__ A0, const float* __restrict__ X0, float* __restrict__ C0,
    const float* __restrict__ A1, const float* __restrict__ X1, float* __restrict__ C1)
{
    const int K = DIM, N = YD;
    const int z = blockIdx.z;
    const int b = z & 7;
    const float* A  = (z < NB) ? A0 : A1;
    const float* Bp = ((z < NB) ? X0 : X1) + (size_t)b * K * N;
    float*       Cp = ((z < NB) ? C0 : C1) + (size_t)b * INNER * N;
    const int n0 = blockIdx.x * 128;
    const int m0 = blockIdx.y * 128;

    __shared__ float As[8][132];
    __shared__ float Bs[8][128];

    const int t = threadIdx.x, tx = t & 15, ty = t >> 4;

    u64 acc[4][8];
#pragma unroll
    for (int i = 0; i < 4; i++)
#pragma unroll
        for (int j = 0; j < 8; j++) acc[i][j] = 0ULL;

    for (int k0 = 0; k0 < K; k0 += 8) {
        {   int m = t >> 1, k4 = (t & 1) * 4;
            float4 a = *(const float4*)&A[(m0 + m) * K + k0 + k4];
            As[k4 + 0][m] = a.x; As[k4 + 1][m] = a.y;
            As[k4 + 2][m] = a.z; As[k4 + 3][m] = a.w;
        }
        {   int kk = t >> 5, n4 = (t & 31) * 4;
            *(float4*)&Bs[kk][n4] = *(const float4*)&Bp[(size_t)(k0 + kk) * N + n0 + n4];
        }
        __syncthreads();
#pragma unroll
        for (int k = 0; k < 8; k++) {
            ulonglong2 av0 = *(const ulonglong2*)&As[k][ty * 8];
            ulonglong2 av1 = *(const ulonglong2*)&As[k][ty * 8 + 4];
            u64 a2[4] = { av0.x, av0.y, av1.x, av1.y };
            float4 b0 = *(const float4*)&Bs[k][tx * 4];
            float4 b1 = *(const float4*)&Bs[k][64 + tx * 4];
            u64 bd[8] = { dup2(b0.x), dup2(b0.y), dup2(b0.z), dup2(b0.w),
                          dup2(b1.x), dup2(b1.y), dup2(b1.z), dup2(b1.w) };
#pragma unroll
            for (int ip = 0; ip < 4; ip++)
#pragma unroll
                for (int jj = 0; jj < 8; jj++)
                    acc[ip][jj] = ffma2(a2[ip], bd[jj], acc[ip][jj]);
        }
        __syncthreads();
    }
#pragma unroll
    for (int ip = 0; ip < 4; ip++) {
        int r0 = m0 + ty * 8 + 2 * ip;
#pragma unroll
        for (int c = 0; c < 2; c++) {
            float4 lo, hi;
            float2 f0 = u2f(acc[ip][c * 4 + 0]), f1 = u2f(acc[ip][c * 4 + 1]);
            float2 f2 = u2f(acc[ip][c * 4 + 2]), f3 = u2f(acc[ip][c * 4 + 3]);
            lo.x = f0.x; lo.y = f1.x; lo.z = f2.x; lo.w = f3.x;
            hi.x = f0.y; hi.y = f1.y; hi.z = f2.y; hi.w = f3.y;
            size_t col = n0 + 64 * c + tx * 4;
            *(float4*)&Cp[(size_t)r0 * N + col]       = lo;
            *(float4*)&Cp[(size_t)(r0 + 1) * N + col] = hi;
        }
    }
}

// =====================================================================
// KV projection (both streams). M=1024,N=256(w),K=4096. BM=128,BN=64,BK=16.
// micro 8m x 4n, m packed pairs.
// =====================================================================
__global__ __launch_bounds__(256) void kvproj_kernel(
    const float* __restrict__ W0, const float* __restrict__ X0, float* __restrict__ C0,
    const float* __restrict__ W1, const float* __restrict__ X1, float* __restrict__ C1)
{
    const int M = 2 * INNER, N = WW, K = DIM * 16;
    const int z = blockIdx.z;
    const int b = z & 7;
    const float* Wkv = (z < NB) ? W0 : W1;
    const float* xp  = ((z < NB) ? X0 : X1) + (size_t)b * DIM * YD;
    float*       Cp  = ((z < NB) ? C0 : C1) + (size_t)b * M * N;
    const int n0 = blockIdx.x * 64;
    const int m0 = blockIdx.y * 128;

    __shared__ float As[16][132];
    __shared__ float Bs[16][68];

    const int t = threadIdx.x, tx = t & 15, ty = t >> 4;

    u64 acc[4][4];
#pragma unroll
    for (int i = 0; i < 4; i++)
#pragma unroll
        for (int j = 0; j < 4; j++) acc[i][j] = 0ULL;

    for (int nt = 0; nt < DIM; nt++) {
        const int k0 = nt * 16;
        {   int m = t >> 1, k8 = (t & 1) * 8;
            float4 a0 = *(const float4*)&Wkv[(size_t)(m0 + m) * K + k0 + k8];
            float4 a1 = *(const float4*)&Wkv[(size_t)(m0 + m) * K + k0 + k8 + 4];
            As[k8 + 0][m] = a0.x; As[k8 + 1][m] = a0.y;
            As[k8 + 2][m] = a0.z; As[k8 + 3][m] = a0.w;
            As[k8 + 4][m] = a1.x; As[k8 + 5][m] = a1.y;
            As[k8 + 6][m] = a1.z; As[k8 + 7][m] = a1.w;
        }
        {   const float* src = xp + (size_t)nt * YD + n0 * 16;
            float4 v = *(const float4*)&src[t * 4];
            int w = t >> 2, pq0 = (t & 3) * 4;
            Bs[pq0 + 0][w] = v.x; Bs[pq0 + 1][w] = v.y;
            Bs[pq0 + 2][w] = v.z; Bs[pq0 + 3][w] = v.w;
        }
        __syncthreads();
#pragma unroll
        for (int k = 0; k < 16; k++) {
            ulonglong2 av0 = *(const ulonglong2*)&As[k][ty * 8];
            ulonglong2 av1 = *(const ulonglong2*)&As[k][ty * 8 + 4];
            u64 a2[4] = { av0.x, av0.y, av1.x, av1.y };
            float4 bb = *(const float4*)&Bs[k][tx * 4];
            u64 bd[4] = { dup2(bb.x), dup2(bb.y), dup2(bb.z), dup2(bb.w) };
#pragma unroll
            for (int ip = 0; ip < 4; ip++)
#pragma unroll
                for (int jj = 0; jj < 4; jj++)
                    acc[ip][jj] = ffma2(a2[ip], bd[jj], acc[ip][jj]);
        }
        __syncthreads();
    }
#pragma unroll
    for (int ip = 0; ip < 4; ip++) {
        int r0 = m0 + ty * 8 + 2 * ip;
        float4 lo, hi;
        float2 f0 = u2f(acc[ip][0]), f1 = u2f(acc[ip][1]);
        float2 f2 = u2f(acc[ip][2]), f3 = u2f(acc[ip][3]);
        lo.x = f0.x; lo.y = f1.x; lo.z = f2.x; lo.w = f3.x;
        hi.x = f0.y; hi.y = f1.y; hi.z = f2.y; hi.w = f3.y;
        *(float4*)&Cp[(size_t)r0 * N + n0 + tx * 4]       = lo;
        *(float4*)&Cp[(size_t)(r0 + 1) * N + n0 + tx * 4] = hi;
    }
}

// =====================================================================
// Attention (both streams): per CTA (64 q rows, h, b, stream).
// K,V staged [d][j] (no transpose), dots block-GEMM micro 4i x 16j,
// softmax via 16-lane shfl, P -> SMEM, PV pairwise-f32x2 micro 4i x 4d.
// =====================================================================
__global__ __launch_bounds__(256) void attn_kernel(
    const float* __restrict__ Q0, const float* __restrict__ KVa, float* __restrict__ O0,
    const float* __restrict__ Q1, const float* __restrict__ KVb, float* __restrict__ O1)
{
    const int z = blockIdx.z;
    const int b = z & 7;
    const float* Q  = (z < NB) ? Q0 : Q1;
    const float* KV = (z < NB) ? KVa : KVb;   // stream0 attends KV1, stream1 attends KV0
    float*       O  = (z < NB) ? O0 : O1;
    const int h  = blockIdx.y;
    const int i0 = blockIdx.x * 64;

    extern __shared__ float sm[];
    float* ks = sm;                    // [64][260]
    float* vs = ks + 64 * 260;         // [64][260]
    float* ps = vs + 64 * 260;         // [64][260]
    float* qs = ps + 64 * 260;         // [64][68]  (qs[d][i])

    const int t = threadIdx.x, tx = t & 15, ty = t >> 4;

    const float* Kb = KV + ((size_t)b * 1024 + h * 64) * WW;
    const float* Vb = KV + ((size_t)b * 1024 + 512 + h * 64) * WW;

    for (int idx = t; idx < 64 * 64; idx += 256) {
        int d = idx >> 6, j4 = (idx & 63) * 4;
        *(float4*)&ks[d * 260 + j4] = *(const float4*)&Kb[d * WW + j4];
        *(float4*)&vs[d * 260 + j4] = *(const float4*)&Vb[d * WW + j4];
    }
    for (int idx = t; idx < 64 * 16; idx += 256) {
        int d = idx >> 4, i4 = (idx & 15) * 4;
        *(float4*)&qs[d * 68 + i4] =
            *(const float4*)&Q[((size_t)b * INNER + h * 64 + d) * YD + i0 + i4];
    }
    __syncthreads();

    // ---- dots: rows i = ty*4+ii, cols j = 64*c + tx*4 + w ----
    u64 s2[4][8];
#pragma unroll
    for (int i = 0; i < 4; i++)
#pragma unroll
        for (int j = 0; j < 8; j++) s2[i][j] = 0ULL;

#pragma unroll 8
    for (int d = 0; d < 64; d++) {
        float4 q4 = *(const float4*)&qs[d * 68 + ty * 4];
        u64 qd[4] = { dup2(q4.x), dup2(q4.y), dup2(q4.z), dup2(q4.w) };
#pragma unroll
        for (int c = 0; c < 4; c++) {
            ulonglong2 kk = *(const ulonglong2*)&ks[d * 260 + c * 64 + tx * 4];
#pragma unroll
            for (int ii = 0; ii < 4; ii++) {
                s2[ii][c * 2 + 0] = ffma2(qd[ii], kk.x, s2[ii][c * 2 + 0]);
                s2[ii][c * 2 + 1] = ffma2(qd[ii], kk.y, s2[ii][c * 2 + 1]);
            }
        }
    }

    // ---- softmax over j (row spread across 16 tx lanes) ----
    float p[4][16];
#pragma unroll
    for (int ii = 0; ii < 4; ii++) {
        float mx = -1e30f;
#pragma unroll
        for (int jp = 0; jp < 8; jp++) {
            float2 f = u2f(s2[ii][jp]);
            p[ii][jp * 2 + 0] = f.x * ASCALE;
            p[ii][jp * 2 + 1] = f.y * ASCALE;
            mx = fmaxf(mx, fmaxf(p[ii][jp * 2], p[ii][jp * 2 + 1]));
        }
#pragma unroll
        for (int off = 8; off; off >>= 1)
            mx = fmaxf(mx, __shfl_xor_sync(0xffffffffu, mx, off));
        float s = 0.f;
#pragma unroll
        for (int w = 0; w < 16; w++) { p[ii][w] = __expf(p[ii][w] - mx); s += p[ii][w]; }
#pragma unroll
        for (int off = 8; off; off >>= 1)
            s += __shfl_xor_sync(0xffffffffu, s, off);
        float inv = 1.f / s;
#pragma unroll
        for (int w = 0; w < 16; w++) p[ii][w] *= inv;
    }
#pragma unroll
    for (int ii = 0; ii < 4; ii++) {
        int row = ty * 4 + ii;
#pragma unroll
        for (int c = 0; c < 4; c++) {
            float4 v;
            v.x = p[ii][c * 4 + 0]; v.y = p[ii][c * 4 + 1];
            v.z = p[ii][c * 4 + 2]; v.w = p[ii][c * 4 + 3];
            *(float4*)&ps[row * 260 + c * 64 + tx * 4] = v;
        }
    }
    __syncthreads();

    // ---- PV pairwise: o[i][d], i = ty*4+ii, d = tx + 16r ----
    u64 o2[4][4];
#pragma unroll
    for (int i = 0; i < 4; i++)
#pragma unroll
        for (int j = 0; j < 4; j++) o2[i][j] = 0ULL;

#pragma unroll 8
    for (int j = 0; j < 256; j += 4) {
        ulonglong2 av[4], bv[4];
#pragma unroll
        for (int ii = 0; ii < 4; ii++)
            av[ii] = *(const ulonglong2*)&ps[(ty * 4 + ii) * 260 + j];
#pragma unroll
        for (int r = 0; r < 4; r++)
            bv[r] = *(const ulonglong2*)&vs[(tx + 16 * r) * 260 + j];
#pragma unroll
        for (int ii = 0; ii < 4; ii++)
#pragma unroll
            for (int r = 0; r < 4; r++) {
                o2[ii][r] = ffma2(av[ii].x, bv[r].x, o2[ii][r]);
                o2[ii][r] = ffma2(av[ii].y, bv[r].y, o2[ii][r]);
            }
    }
#pragma unroll
    for (int ii = 0; ii < 4; ii++) {
        size_t base = (((size_t)b * YD + i0 + ty * 4 + ii) * HH + h) * 64;
#pragma unroll
        for (int r = 0; r < 4; r++) {
            float2 f = u2f(o2[ii][r]);
            O[base + tx + 16 * r] = f.x + f.y;
        }
    }
}

// =====================================================================
// Out proj (NT, both phases) + residual fuse. M=256,N=4096,K=512x2.
// micro 8m x 8n, m packed pairs.
// =====================================================================
__global__ __launch_bounds__(256) void outproj_kernel(
    const float* __restrict__ W0, const float* __restrict__ O0,
    const float* __restrict__ W1, const float* __restrict__ O1,
    const float* __restrict__ b0, const float* __restrict__ b1,
    const float* __restrict__ x0, const float* __restrict__ x1,
    float* __restrict__ out)
{
    const int b  = blockIdx.z;
    const int n0 = blockIdx.x * 128;
    const int m0 = blockIdx.y * 128;

    __shared__ float Ws[16][132];
    __shared__ float Bs[16][132];

    const int t = threadIdx.x, tx = t & 15, ty = t >> 4;

    u64 acc[4][8];
#pragma unroll
    for (int i = 0; i < 4; i++)
#pragma unroll
        for (int j = 0; j < 8; j++) acc[i][j] = 0ULL;

    const float* Ops[2]  = { O0 + (size_t)b * YD * INNER, O1 + (size_t)b * YD * INNER };
    const float* Wsrc[2] = { W0, W1 };

    for (int ph = 0; ph < 2; ph++) {
        const float* W  = Wsrc[ph];
        const float* Op = Ops[ph];
        for (int k0 = 0; k0 < INNER; k0 += 16) {
            {   int m = t >> 1, k8 = (t & 1) * 8;
                float4 a0 = *(const float4*)&W[(size_t)(m0 + m) * INNER + k0 + k8];
                float4 a1 = *(const float4*)&W[(size_t)(m0 + m) * INNER + k0 + k8 + 4];
                Ws[k8 + 0][m] = a0.x; Ws[k8 + 1][m] = a0.y;
                Ws[k8 + 2][m] = a0.z; Ws[k8 + 3][m] = a0.w;
                Ws[k8 + 4][m] = a1.x; Ws[k8 + 5][m] = a1.y;
                Ws[k8 + 6][m] = a1.z; Ws[k8 + 7][m] = a1.w;
            }
            {   int n = t >> 1, k8 = (t & 1) * 8;
                float4 a0 = *(const float4*)&Op[(size_t)(n0 + n) * INNER + k0 + k8];
                float4 a1 = *(const float4*)&Op[(size_t)(n0 + n) * INNER + k0 + k8 + 4];
                Bs[k8 + 0][n] = a0.x; Bs[k8 + 1][n] = a0.y;
                Bs[k8 + 2][n] = a0.z; Bs[k8 + 3][n] = a0.w;
                Bs[k8 + 4][n] = a1.x; Bs[k8 + 5][n] = a1.y;
                Bs[k8 + 6][n] = a1.z; Bs[k8 + 7][n] = a1.w;
            }
            __syncthreads();
#pragma unroll
            for (int k = 0; k < 16; k++) {
                ulonglong2 av0 = *(const ulonglong2*)&Ws[k][ty * 8];
                ulonglong2 av1 = *(const ulonglong2*)&Ws[k][ty * 8 + 4];
                u64 a2[4] = { av0.x, av0.y, av1.x, av1.y };
                float4 c0 = *(const float4*)&Bs[k][tx * 4];
                float4 c1 = *(const float4*)&Bs[k][64 + tx * 4];
                u64 bd[8] = { dup2(c0.x), dup2(c0.y), dup2(c0.z), dup2(c0.w),
                              dup2(c1.x), dup2(c1.y), dup2(c1.z), dup2(c1.w) };
#pragma unroll
                for (int ip = 0; ip < 4; ip++)
#pragma unroll
                    for (int jj = 0; jj < 8; jj++)
                        acc[ip][jj] = ffma2(a2[ip], bd[jj], acc[ip][jj]);
            }
            __syncthreads();
        }
    }

#pragma unroll
    for (int ip = 0; ip < 4; ip++) {
        int r0 = m0 + ty * 8 + 2 * ip;
        float bias0 = 0.5f * (b0[r0] + b1[r0]);
        float bias1 = 0.5f * (b0[r0 + 1] + b1[r0 + 1]);
#pragma unroll
        for (int c = 0; c < 2; c++) {
            float4 lo, hi;
            float2 f0 = u2f(acc[ip][c * 4 + 0]), f1 = u2f(acc[ip][c * 4 + 1]);
            float2 f2 = u2f(acc[ip][c * 4 + 2]), f3 = u2f(acc[ip][c * 4 + 3]);
            lo.x = f0.x; lo.y = f1.x; lo.z = f2.x; lo.w = f3.x;
            hi.x = f0.y; hi.y = f1.y; hi.z = f2.y; hi.w = f3.y;
            size_t col = n0 + 64 * c + tx * 4;
            size_t i0x = ((size_t)b * DIM + r0) * YD + col;
            size_t i1x = ((size_t)b * DIM + r0 + 1) * YD + col;
            float4 xa0 = *(const float4*)&x0[i0x], xb0 = *(const float4*)&x1[i0x];
            float4 xa1 = *(const float4*)&x0[i1x], xb1 = *(const float4*)&x1[i1x];
            float4 r;
            r.x = 0.5f * (lo.x + xa0.x + xb0.x) + bias0;
            r.y = 0.5f * (lo.y + xa0.y + xb0.y) + bias0;
            r.z = 0.5f * (lo.z + xa0.z + xb0.z) + bias0;
            r.w = 0.5f * (lo.w + xa0.w + xb0.w) + bias0;
            *(float4*)&out[i0x] = r;
            r.x = 0.5f * (hi.x + xa1.x + xb1.x) + bias1;
            r.y = 0.5f * (hi.y + xa1.y + xb1.y) + bias1;
            r.z = 0.5f * (hi.z + xa1.z + xb1.z) + bias1;
            r.w = 0.5f * (hi.w + xa1.w + xb1.w) + bias1;
            *(float4*)&out[i1x] = r;
        }
    }
}

// =====================================================================
extern "C" void kernel_launch(void* const* d_in, const int* in_sizes, int n_in,
                              void* d_out, int out_size)
{
    const float* x0    = (const float*)d_in[0];
    const float* x1    = (const float*)d_in[1];
    const float* Wq0   = (const float*)d_in[2];
    const float* Wkv0  = (const float*)d_in[3];
    const float* Wq1   = (const float*)d_in[4];
    const float* Wkv1  = (const float*)d_in[5];
    const float* Wout0 = (const float*)d_in[6];
    const float* bout0 = (const float*)d_in[7];
    const float* Wout1 = (const float*)d_in[8];
    const float* bout1 = (const float*)d_in[9];
    float* out = (float*)d_out;

    float *Q0, *Q1, *KV0, *KV1, *O0, *O1;
    cudaGetSymbolAddress((void**)&Q0,  g_Q0);
    cudaGetSymbolAddress((void**)&Q1,  g_Q1);
    cudaGetSymbolAddress((void**)&KV0, g_KV0);
    cudaGetSymbolAddress((void**)&KV1, g_KV1);
    cudaGetSymbolAddress((void**)&O0,  g_O0);
    cudaGetSymbolAddress((void**)&O1,  g_O1);

    const int attn_smem = (3 * 64 * 260 + 64 * 68) * (int)sizeof(float);   // 217088
    cudaFuncSetAttribute(attn_kernel, cudaFuncAttributeMaxDynamicSharedMemorySize, attn_smem);

    dim3 blk(256);
    qproj_kernel<<<dim3(YD / 128, INNER / 128, 2 * NB), blk>>>(Wq0, x0, Q0, Wq1, x1, Q1);
    kvproj_kernel<<<dim3(WW / 64, (2 * INNER) / 128, 2 * NB), blk>>>(Wkv0, x0, KV0, Wkv1, x1, KV1);
    // stream0: attend(Q0, KV1) -> O0 ; stream1: attend(Q1, KV0) -> O1
    attn_kernel<<<dim3(YD / 64, HH, 2 * NB), blk, attn_smem>>>(Q0, KV1, O0, Q1, KV0, O1);
    outproj_kernel<<<dim3(YD / 128, DIM / 128, NB), blk>>>(
        Wout0, O0, Wout1, O1, bout0, bout1, x0, x1, out);
}